// round 8
// baseline (speedup 1.0000x reference)
#include <cuda_runtime.h>

#define GS      20
#define PARAM   40
#define NN      (GS * PARAM)     // 800
#define NSYS    80               // B*A
#define MST     44               // padded smem matrix stride (rows 16B-aligned)

// ---------------------------------------------------------------------------
// One CTA per system, 800 threads, 1 element/thread (t <-> (g,p)).
//
// P = I(x)S + M(x)Ng,  F = S/2 - I.
// Bpre = 0.5(I-F)(I+F^2+F^4)  =>  Bpre*S = I - F^6  (bias ~1e-5..1e-4, OK).
// Transformed: (I + K)x = b,  K = M(x)C,  C = Bpre*Ng,  b = (I(x)Bpre)v.
// Degree-5 Neumann evaluated with K^2 = M^2 (x) C^2:
//   u0 = b + K^2 b;  u = b + K^2 u0;  x = u - K u;  then clip.
// Identical polynomial to 5 Richardson sweeps, in 6 apply-phases.
// ---------------------------------------------------------------------------

#define GM_PLAIN 0   // D = A*Bm
#define GM_H     1   // D = A*Bm + A + I   (H = G^2 + G + I, A=B=G)
#define GM_BF    2   // D = 0.5*(Bm - A*Bm)

// 40x40 GEMM on stride-MST smem, 800 threads, 1x2 tiles, float4 A-row reads.
template <int MODE>
__device__ __forceinline__ void gemm40(float* __restrict__ D,
                                       const float* __restrict__ A,
                                       const float* __restrict__ B,
                                       int t)
{
    const int r  = t / 20;          // 0..39
    const int c0 = (t % 20) * 2;    // 0,2,...,38
    const float4* Arow = (const float4*)&A[r * MST];
    float a0 = 0.f, a1 = 0.f;
    #pragma unroll
    for (int k4 = 0; k4 < 10; ++k4) {
        float4 a4 = Arow[k4];
        float2 b0 = *(const float2*)&B[(4 * k4 + 0) * MST + c0];
        float2 b1 = *(const float2*)&B[(4 * k4 + 1) * MST + c0];
        float2 b2 = *(const float2*)&B[(4 * k4 + 2) * MST + c0];
        float2 b3 = *(const float2*)&B[(4 * k4 + 3) * MST + c0];
        a0 = fmaf(a4.x, b0.x, a0);  a1 = fmaf(a4.x, b0.y, a1);
        a0 = fmaf(a4.y, b1.x, a0);  a1 = fmaf(a4.y, b1.y, a1);
        a0 = fmaf(a4.z, b2.x, a0);  a1 = fmaf(a4.z, b2.y, a1);
        a0 = fmaf(a4.w, b3.x, a0);  a1 = fmaf(a4.w, b3.y, a1);
    }
    float2 o;
    if (MODE == GM_H) {
        o.x = a0 + A[r * MST + c0];
        o.y = a1 + A[r * MST + c0 + 1];
        if (r == c0)     o.x += 1.0f;
        if (r == c0 + 1) o.y += 1.0f;
    } else if (MODE == GM_BF) {
        o.x = 0.5f * (B[r * MST + c0]     - a0);
        o.y = 0.5f * (B[r * MST + c0 + 1] - a1);
    } else {
        o.x = a0; o.y = a1;
    }
    *(float2*)&D[r * MST + c0] = o;
}

// row-vector inner product: dot(Mat[p,:], vec[g,:]) with float4 reads
__device__ __forceinline__ float rowdot40(const float* __restrict__ Mrow,
                                          const float* __restrict__ vrow)
{
    const float4* m4 = (const float4*)Mrow;
    const float4* v4 = (const float4*)vrow;
    float acc = 0.f;
    #pragma unroll
    for (int i = 0; i < 10; ++i) {
        float4 m = m4[i], v = v4[i];
        acc = fmaf(m.x, v.x, acc);
        acc = fmaf(m.y, v.y, acc);
        acc = fmaf(m.z, v.z, acc);
        acc = fmaf(m.w, v.w, acc);
    }
    return acc;
}

// column combine: sum_g2 Mrow[g2] * Tbuf[g2*PARAM + p], GS=20, M row via float4
__device__ __forceinline__ float coldot20(const float* __restrict__ Mrow,
                                          const float* __restrict__ Tcol_p)
{
    const float4* m4 = (const float4*)Mrow;   // 5 float4 = 20 floats
    float acc = 0.f;
    #pragma unroll
    for (int i = 0; i < 5; ++i) {
        float4 m = m4[i];
        acc = fmaf(m.x, Tcol_p[(4 * i + 0) * PARAM], acc);
        acc = fmaf(m.y, Tcol_p[(4 * i + 1) * PARAM], acc);
        acc = fmaf(m.z, Tcol_p[(4 * i + 2) * PARAM], acc);
        acc = fmaf(m.w, Tcol_p[(4 * i + 3) * PARAM], acc);
    }
    return acc;
}

__global__ __launch_bounds__(NN, 1)
void gliam_fused_kernel(const float* __restrict__ mat,        // (80,20,20)
                        const float* __restrict__ val,        // (80,800)
                        const float* __restrict__ selfintact, // (40,40)
                        const float* __restrict__ neigintact, // (40,40)
                        float* __restrict__ out)              // (80,800)
{
    __shared__ __align__(16) float mF [PARAM * MST];  // F; later C2
    __shared__ __align__(16) float mG [PARAM * MST];  // G = F^2; later C
    __shared__ __align__(16) float mH [PARAM * MST];  // H = I + G + G^2
    __shared__ __align__(16) float mB [PARAM * MST];  // Bpre
    __shared__ __align__(16) float mNg[PARAM * MST];  // Ng
    __shared__ __align__(16) float sx [NN];           // b, later u
    __shared__ __align__(16) float sV [NN];           // v, later u0
    __shared__ __align__(16) float sT [NN];           // T scratch
    __shared__ __align__(16) float sM [GS * GS];      // M
    __shared__ __align__(16) float sM2[GS * GS];      // M^2

    const int sys = blockIdx.x;
    const int t   = threadIdx.x;     // 0..799
    const int g   = t / PARAM;       // 0..19
    const int p   = t % PARAM;       // 0..39

    // ---- phase 0: stage inputs ----
    {
        int i0 = t, i1 = t + NN;
        int r0 = i0 / PARAM, c0 = i0 % PARAM;
        int r1 = i1 / PARAM, c1 = i1 % PARAM;
        mF [r0 * MST + c0] = 0.5f * selfintact[i0] - (r0 == c0 ? 1.0f : 0.0f);
        mF [r1 * MST + c1] = 0.5f * selfintact[i1] - (r1 == c1 ? 1.0f : 0.0f);
        mNg[r0 * MST + c0] = neigintact[i0];
        mNg[r1 * MST + c1] = neigintact[i1];
        sV[t] = val[sys * NN + t];
        if (t < GS * GS) sM[t] = mat[sys * GS * GS + t];
    }
    __syncthreads();

    // ---- phase 1: G = F^2 ; also M2 = M*M (threads < 400) ----
    gemm40<GM_PLAIN>(mG, mF, mF, t);
    if (t < GS * GS) {
        int i = t / GS, j = t % GS;
        float acc = 0.f;
        #pragma unroll
        for (int k = 0; k < GS; ++k)
            acc = fmaf(sM[i * GS + k], sM[k * GS + j], acc);
        sM2[t] = acc;
    }
    __syncthreads();

    // ---- phase 2: H = I + G + G^2 ----
    gemm40<GM_H>(mH, mG, mG, t);
    __syncthreads();

    // ---- phase 3: Bpre = 0.5*(H - F*H) ----
    gemm40<GM_BF>(mB, mF, mH, t);
    __syncthreads();

    // ---- phase 4: C = Bpre*Ng (into mG) ; b = (I(x)Bpre)v ----
    gemm40<GM_PLAIN>(mG, mB, mNg, t);
    float b = rowdot40(&mB[p * MST], &sV[g * PARAM]);
    __syncthreads();                 // (sV content still v; b not yet in smem)
    sx[t] = b;
    __syncthreads();

    // ---- phase 5: C2 = C*C (into mF) ----
    gemm40<GM_PLAIN>(mF, mG, mG, t);
    __syncthreads();

    // ---- apply phases ----
    // P1: T = (I(x)C2) b
    sT[t] = rowdot40(&mF[p * MST], &sx[g * PARAM]);
    __syncthreads();
    // P2: u0 = b + (M2(x)I) T
    float u0 = b + coldot20(&sM2[g * GS], &sT[p]);
    __syncthreads();                 // sT consumed
    sV[t] = u0;                      // v dead -> u0
    __syncthreads();
    // P3: T = (I(x)C2) u0
    sT[t] = rowdot40(&mF[p * MST], &sV[g * PARAM]);
    __syncthreads();
    // P4: u = b + (M2(x)I) T
    float u = b + coldot20(&sM2[g * GS], &sT[p]);
    __syncthreads();                 // sT consumed; sx (b rows) dead
    sx[t] = u;
    __syncthreads();
    // P5: T = (I(x)C) u
    sT[t] = rowdot40(&mG[p * MST], &sx[g * PARAM]);
    __syncthreads();
    // P6: x = u - (M(x)I) T ; clip ; store
    float x = u - coldot20(&sM[g * GS], &sT[p]);
    x = fminf(fmaxf(x, -1.0f), 1.0f);
    out[sys * NN + t] = x;
}

extern "C" void kernel_launch(void* const* d_in, const int* in_sizes, int n_in,
                              void* d_out, int out_size)
{
    const float* mat        = (const float*)d_in[0];
    const float* val        = (const float*)d_in[1];
    const float* selfintact = (const float*)d_in[2];
    const float* neigintact = (const float*)d_in[3];
    float* out = (float*)d_out;

    gliam_fused_kernel<<<NSYS, NN>>>(mat, val, selfintact, neigintact, out);
}

// round 10
// speedup vs baseline: 1.2434x; 1.2434x over previous
#include <cuda_runtime.h>

#define GS      20
#define PARAM   40
#define NN      (GS * PARAM)     // 800
#define NSYS    80               // B*A
#define MST     44               // padded matrix stride (f4-aligned, good bank spread)
#define NITER   4                // sweeps: trunc err ~ rho^5 ~ 7.6e-5

// ---------------------------------------------------------------------------
// One CTA per system, 800 threads.
// P = I(x)S + M(x)Ng,  F = S/2 - I.  Bpre = 0.5(I-F)(I+F^2+F^4): BS = I-F^6
// (bias 1.5e-5, measured R6).  x = b - (M(x)C)x,  C=Bpre*Ng, b=(I(x)Bpre)v.
// 4 Richardson sweeps.  Prep GEMMs: warp-cooperative tiling at the FMA floor.
// ---------------------------------------------------------------------------

#define GM_PLAIN 0   // D = A*Bm
#define GM_H     1   // D = A*Bm + A + I      (H = G^2 + G + I, A=B=G)
#define GM_BF    2   // D = 0.5*(Bm - A*Bm)   (B = 0.5*(H - F*H))

// Warp-cooperative 40x40 GEMM, 10 warps (t < 320).
// Warp w: rows 4w..4w+3.  lane -> rr = lane>>3 (row), cc = lane&7.
// Cols per thread: {2cc, 2cc+1}, {2cc+16, 2cc+17}, and {2cc+32, 2cc+33} if cc<4.
// B k-row reads: 8 distinct float2 per instr = 1 conflict-free wavefront.
// A reads: float4 per 4 k's, 4 distinct rows -> broadcast, 1 wavefront.
template <int MODE>
__device__ __forceinline__ void gemm40w(float* __restrict__ D,
                                        const float* __restrict__ A,
                                        const float* __restrict__ B,
                                        int t)
{
    if (t >= 320) return;
    const int lane = t & 31;
    const int rr   = lane >> 3;          // 0..3
    const int cc   = lane & 7;           // 0..7
    const int r    = 4 * (t >> 5) + rr;  // 0..39
    const int c0   = 2 * cc;             // 0..15
    const int c1   = c0 + 16;            // 16..31
    const int c2   = c0 + 32;            // 32..39 (cc<4 only)
    const bool has2 = (cc < 4);

    float a00 = 0.f, a01 = 0.f, a10 = 0.f, a11 = 0.f, a20 = 0.f, a21 = 0.f;
    const float4* Arow = (const float4*)(A + r * MST);
    #pragma unroll
    for (int k4 = 0; k4 < 10; ++k4) {
        float4 a4 = Arow[k4];
        #pragma unroll
        for (int j = 0; j < 4; ++j) {
            float av = (j == 0) ? a4.x : (j == 1) ? a4.y : (j == 2) ? a4.z : a4.w;
            const float* Bk = B + (4 * k4 + j) * MST;
            float2 b0 = *(const float2*)(Bk + c0);
            float2 b1 = *(const float2*)(Bk + c1);
            a00 = fmaf(av, b0.x, a00);  a01 = fmaf(av, b0.y, a01);
            a10 = fmaf(av, b1.x, a10);  a11 = fmaf(av, b1.y, a11);
            if (has2) {
                float2 b2 = *(const float2*)(Bk + c2);
                a20 = fmaf(av, b2.x, a20);  a21 = fmaf(av, b2.y, a21);
            }
        }
    }

    // epilogue + store (float2)
    #pragma unroll
    for (int s = 0; s < 3; ++s) {
        if (s == 2 && !has2) break;
        int  c  = (s == 0) ? c0 : (s == 1) ? c1 : c2;
        float v0 = (s == 0) ? a00 : (s == 1) ? a10 : a20;
        float v1 = (s == 0) ? a01 : (s == 1) ? a11 : a21;
        float2 o;
        if (MODE == GM_H) {
            o.x = v0 + A[r * MST + c]     + (r == c     ? 1.0f : 0.0f);
            o.y = v1 + A[r * MST + c + 1] + (r == c + 1 ? 1.0f : 0.0f);
        } else if (MODE == GM_BF) {
            o.x = 0.5f * (B[r * MST + c]     - v0);
            o.y = 0.5f * (B[r * MST + c + 1] - v1);
        } else {
            o.x = v0; o.y = v1;
        }
        *(float2*)(D + r * MST + c) = o;
    }
}

// dot(Mat[p,:], vec[g,:]) with float4 reads (stride-MST matrix, stride-40 vec)
__device__ __forceinline__ float rowdot40(const float* __restrict__ Mrow,
                                          const float* __restrict__ vrow)
{
    const float4* m4 = (const float4*)Mrow;
    const float4* v4 = (const float4*)vrow;
    float acc = 0.f;
    #pragma unroll
    for (int i = 0; i < 10; ++i) {
        float4 m = m4[i], v = v4[i];
        acc = fmaf(m.x, v.x, acc);
        acc = fmaf(m.y, v.y, acc);
        acc = fmaf(m.z, v.z, acc);
        acc = fmaf(m.w, v.w, acc);
    }
    return acc;
}

__global__ __launch_bounds__(NN, 1)
void gliam_fused_kernel(const float* __restrict__ mat,        // (80,20,20)
                        const float* __restrict__ val,        // (80,800)
                        const float* __restrict__ selfintact, // (40,40)
                        const float* __restrict__ neigintact, // (40,40)
                        float* __restrict__ out)              // (80,800)
{
    __shared__ __align__(16) float mF [PARAM * MST];  // F = S/2 - I
    __shared__ __align__(16) float mG [PARAM * MST];  // G = F^2
    __shared__ __align__(16) float mH [PARAM * MST];  // H = I + G + G^2
    __shared__ __align__(16) float mB [PARAM * MST];  // Bpre
    __shared__ __align__(16) float mNg[PARAM * MST];  // Ng
    __shared__ __align__(16) float mC [PARAM * MST];  // C = Bpre*Ng
    __shared__ __align__(16) float sx [NN];           // iterate
    __shared__ __align__(16) float sT [NN];           // T scratch
    __shared__ __align__(16) float sV [NN];           // v
    __shared__ __align__(16) float sM [GS * GS];      // M

    const int sys = blockIdx.x;
    const int t   = threadIdx.x;     // 0..799
    const int g   = t / PARAM;       // 0..19
    const int p   = t % PARAM;       // 0..39

    // ---- stage inputs ----
    {
        int i0 = t, i1 = t + NN;
        int r0 = i0 / PARAM, c0 = i0 % PARAM;
        int r1 = i1 / PARAM, c1 = i1 % PARAM;
        mF [r0 * MST + c0] = 0.5f * selfintact[i0] - (r0 == c0 ? 1.0f : 0.0f);
        mF [r1 * MST + c1] = 0.5f * selfintact[i1] - (r1 == c1 ? 1.0f : 0.0f);
        mNg[r0 * MST + c0] = neigintact[i0];
        mNg[r1 * MST + c1] = neigintact[i1];
        sV[t] = val[sys * NN + t];
        if (t < GS * GS) sM[t] = mat[sys * GS * GS + t];
    }
    __syncthreads();

    // ---- prep: 4 warp-cooperative GEMMs ----
    gemm40w<GM_PLAIN>(mG, mF, mF, t);   __syncthreads();  // G = F^2
    gemm40w<GM_H    >(mH, mG, mG, t);   __syncthreads();  // H = I + G + G^2
    gemm40w<GM_BF   >(mB, mF, mH, t);   __syncthreads();  // Bpre = 0.5(H - F*H)
    gemm40w<GM_PLAIN>(mC, mB, mNg, t);                    // C = Bpre*Ng
    // b = (I(x)Bpre) v for this element (mB ready; all 800 threads)
    float b = rowdot40(&mB[p * MST], &sV[g * PARAM]);
    __syncthreads();
    sx[t] = b;                        // x0 = b
    __syncthreads();                  // mC + sx visible

    // ---- C[p,:] into registers ----
    float4 creg[10];
    #pragma unroll
    for (int i = 0; i < 10; ++i)
        creg[i] = *(const float4*)&mC[p * MST + 4 * i];

    const float*  Mrow = &sM[g * GS];
    const float4* xrow = (const float4*)&sx[g * PARAM];

    // ---- Richardson sweeps: x <- b - (M (x) C) x ----
    #pragma unroll 1
    for (int it = 0; it < NITER; ++it) {
        // Phase A: T[g,p] = sum_q C[p,q] x[g,q]
        float tv = 0.f;
        #pragma unroll
        for (int i = 0; i < 10; ++i) {
            float4 c  = creg[i];
            float4 x4 = xrow[i];        // broadcast within g-group
            tv = fmaf(c.x, x4.x, tv);
            tv = fmaf(c.y, x4.y, tv);
            tv = fmaf(c.z, x4.z, tv);
            tv = fmaf(c.w, x4.w, tv);
        }
        sT[t] = tv;
        __syncthreads();

        // Phase B: x[g,p] = b - sum_g2 M[g,g2] T[g2,p]
        float acc = b;
        #pragma unroll
        for (int g2 = 0; g2 < GS; ++g2)
            acc = fmaf(-Mrow[g2], sT[g2 * PARAM + p], acc);  // M bcast, T conflict-free

        if (it == NITER - 1) {
            acc = fminf(fmaxf(acc, -1.0f), 1.0f);   // advrelu == clip
            out[sys * NN + t] = acc;
        } else {
            __syncthreads();
            sx[t] = acc;
            __syncthreads();
        }
    }
}

extern "C" void kernel_launch(void* const* d_in, const int* in_sizes, int n_in,
                              void* d_out, int out_size)
{
    const float* mat        = (const float*)d_in[0];
    const float* val        = (const float*)d_in[1];
    const float* selfintact = (const float*)d_in[2];
    const float* neigintact = (const float*)d_in[3];
    float* out = (float*)d_out;

    gliam_fused_kernel<<<NSYS, NN>>>(mat, val, selfintact, neigintact, out);
}